// round 10
// baseline (speedup 1.0000x reference)
#include <cuda_runtime.h>
#include <cuda_bf16.h>
#include <cstdint>

// Problem constants (fixed shapes from reference)
#define T_STEPS 32768
#define D_IN    1024
#define U_HID   1024
#define NG      4096   // 4*U

#define N_LSTM_CTAS 128
#define ROW_TILES   256   // 32768 / 128
#define COL_TILES   32    // 4096 / 128
#define N_TILES     (ROW_TILES * COL_TILES)

// ---------------- static device scratch (no allocs allowed) ----------------
__device__ float              g_zx[(size_t)T_STEPS * NG];  // x@kernel + bias (row-major by t)
// packed hidden state: lo32 = h bits, hi32 = step tag. Double-buffered by parity.
__device__ unsigned long long g_hpk[2][U_HID];
__device__ unsigned           g_rowready[ROW_TILES];       // per-row-tile completion counters

// ============================================================================
// State init (runs every launch: graph replays reuse device globals)
// ============================================================================
__global__ void init_state() {
    const int i = threadIdx.x;
    if (i < U_HID) {
        g_hpk[0][i] = 0ull;                   // h=0, tag=0 -> step 0 matches instantly
        g_hpk[1][i] = 0x8000000000000000ull;  // tag never matches a real step
    }
    if (i < ROW_TILES) g_rowready[i] = 0u;
}

// ============================================================================
// MEGA-KERNEL: CTAs 0..127 = persistent LSTM recurrence; CTAs 128.. = GEMM
// producers computing zx tiles row-tile-major, publishing via red.release.
// ============================================================================
#define GBM 128
#define GBN 128
#define GBK 16

__global__ __launch_bounds__(1024, 1) void mega(
    const float* __restrict__ x,     // [T, D]
    const float* __restrict__ kw,    // [D, 4U]
    const float* __restrict__ bias,  // [4U]
    const float* __restrict__ Rw,    // [U, 4U]
    float* __restrict__ out,         // [T, U]
    int nGemm)
{
    // ---- shared memory (union by role: each CTA touches only its own set) ----
    __shared__ float As[2][GBK][GBM + 4];
    __shared__ float Bs[2][GBK][GBN];
    __shared__ __align__(16) float sh_h[U_HID];
    __shared__ float sp[2][32 * 33];
    __shared__ float zs[32];

    const int tid = threadIdx.x;

    // ========================== GEMM producer role ==========================
    if (blockIdx.x >= N_LSTM_CTAS) {
        const int rank = blockIdx.x - N_LSTM_CTAS;

        const int aRow = tid >> 3;          // 0..127
        const int ac2  = (tid & 7) * 2;     // 0,2,..,14
        const int bRow = tid >> 6;          // 0..15
        const int bc2  = (tid & 63) * 2;    // 0,2,..,126
        const int tx   = tid & 31;          // col/4
        const int ty   = tid >> 5;          // row/4

        for (int tt = rank; tt < N_TILES; tt += nGemm) {
            const int rowT = tt >> 5;       // row-tile-major => rows ready ascending
            const int colT = tt & 31;
            const int cRow = rowT * GBM;
            const int cCol = colT * GBN;
            const float* Ap = x  + (size_t)cRow * D_IN;
            const float* Bp = kw + cCol;

            float acc[4][4];
#pragma unroll
            for (int i = 0; i < 4; ++i)
#pragma unroll
                for (int j = 0; j < 4; ++j) acc[i][j] = 0.f;

            float2 ra, rb;
            auto loadG = [&](int kt) {
                ra = *(const float2*)&Ap[(size_t)aRow * D_IN + kt * GBK + ac2];
                rb = *(const float2*)&Bp[(size_t)(kt * GBK + bRow) * NG + bc2];
            };
            auto storeS = [&](int buf) {
                As[buf][ac2][aRow]     = ra.x;
                As[buf][ac2 + 1][aRow] = ra.y;
                *(float2*)&Bs[buf][bRow][bc2] = rb;
            };

            loadG(0);
            storeS(0);
            __syncthreads();

            const int nT = D_IN / GBK;  // 64
            for (int kt = 0; kt < nT; ++kt) {
                const int buf = kt & 1;
                if (kt + 1 < nT) loadG(kt + 1);
#pragma unroll
                for (int k = 0; k < GBK; ++k) {
                    float4 av = *(const float4*)&As[buf][k][ty * 4];
                    float4 bv = *(const float4*)&Bs[buf][k][tx * 4];
                    float ar[4] = {av.x, av.y, av.z, av.w};
                    float br[4] = {bv.x, bv.y, bv.z, bv.w};
#pragma unroll
                    for (int i = 0; i < 4; ++i)
#pragma unroll
                        for (int j = 0; j < 4; ++j)
                            acc[i][j] = fmaf(ar[i], br[j], acc[i][j]);
                }
                if (kt + 1 < nT) storeS(buf ^ 1);
                __syncthreads();
            }

            // epilogue: + bias, coalesced float4 stores, row-major by t
            float4 bb4 = *(const float4*)&bias[cCol + tx * 4];
            float bb[4] = {bb4.x, bb4.y, bb4.z, bb4.w};
#pragma unroll
            for (int i = 0; i < 4; ++i) {
                const int r = cRow + ty * 4 + i;
                float4 o = make_float4(acc[i][0] + bb[0], acc[i][1] + bb[1],
                                       acc[i][2] + bb[2], acc[i][3] + bb[3]);
                *(float4*)&g_zx[(size_t)r * NG + cCol + tx * 4] = o;
            }
            __syncthreads();          // all stores of this tile issued
            if (tid == 0) {
                __threadfence();      // gpu-scope: make tile stores visible
                asm volatile("red.release.gpu.global.add.u32 [%0], %1;"
                             :: "l"(&g_rowready[rowT]), "r"(1u) : "memory");
            }
            __syncthreads();
        }
        return;
    }

    // ========================== LSTM recurrence role ==========================
    const int w   = tid >> 5;
    const int l   = tid & 31;
    const int u0  = blockIdx.x * 8;
    // stage-1 column for lane l; stage-2 column for warp w
    const int col  = ((l >> 3) << 10) + u0 + (l & 7);
    const int col2 = ((w >> 3) << 10) + u0 + (w & 7);

    // packed weight pairs: W2[m] = {R[32w+2m][col], R[32w+2m+1][col]}
    unsigned long long W2[16];
    {
        const float* wp = Rw + ((size_t)(w << 5)) * NG + col;
#pragma unroll
        for (int m = 0; m < 16; ++m) {
            float w0 = wp[(size_t)(2 * m) * NG];
            float w1 = wp[(size_t)(2 * m + 1) * NG];
            asm("mov.b64 %0, {%1, %2};" : "=l"(W2[m]) : "f"(w0), "f"(w1));
        }
    }

    float cst = 0.f;                       // cell state (warp 0, lanes 0..7)
    const float* zxp = g_zx + col2;

    // zx readiness tracking (only l==0 lanes use it)
    int zreadyT = 0;
    auto wait_tile = [&](int tile) {
        unsigned v;
        do {
            asm volatile("ld.acquire.gpu.global.u32 %0, [%1];"
                         : "=r"(v) : "l"(&g_rowready[tile]) : "memory");
        } while (v < (unsigned)COL_TILES);
    };

    float zxv = 0.f;
    if (l == 0) {               // initial zx (row 0) — wait for tile 0
        wait_tile(0);
        zreadyT = 1;
        zxv = __ldg(zxp);
    }

    const int e = (w << 5) + l;            // element this lane polls
    const int jq = l >> 3;                 // quarter index for stage-2 reduce
    const int jj = l & 7;

    for (int t = 0; t < T_STEPS; ++t) {
        // prefetch next step's zx early (gated by tile readiness)
        float zxn = 0.f;
        if (l == 0 && t + 1 < T_STEPS) {
            const int tl = (t + 1) >> 7;
            if (tl >= zreadyT) { wait_tile(tl); zreadyT = tl + 1; }
            zxn = __ldg(&zxp[(size_t)(t + 1) * NG]);
        }

        // poll the packed {h, tag} word; tag==t => h is the step-t value
        {
            const unsigned long long* src = &g_hpk[t & 1][e];
            unsigned long long pk;
            do {
                asm volatile("ld.volatile.global.u64 %0, [%1];"
                             : "=l"(pk) : "l"(src));
            } while ((unsigned)(pk >> 32) != (unsigned)t);
            sh_h[e] = __uint_as_float((unsigned)pk);
        }
        __syncwarp();

        float* const spb = sp[t & 1];      // step-parity buffer

        // stage 1: packed-f32x2 partial dot over rows [32w,32w+32) for `col`
        unsigned long long acc0 = 0ull, acc1 = 0ull;
        const ulonglong2* h2 = reinterpret_cast<const ulonglong2*>(sh_h + (w << 5));
#pragma unroll
        for (int k = 0; k < 8; ++k) {
            ulonglong2 hv = h2[k];  // all lanes same address -> smem broadcast
            asm("fma.rn.f32x2 %0, %1, %2, %3;"
                : "=l"(acc0) : "l"(hv.x), "l"(W2[2 * k]),     "l"(acc0));
            asm("fma.rn.f32x2 %0, %1, %2, %3;"
                : "=l"(acc1) : "l"(hv.y), "l"(W2[2 * k + 1]), "l"(acc1));
        }
        float a0, a1, b0, b1;
        asm("mov.b64 {%0, %1}, %2;" : "=f"(a0), "=f"(a1) : "l"(acc0));
        asm("mov.b64 {%0, %1}, %2;" : "=f"(b0), "=f"(b1) : "l"(acc1));
        spb[l * 33 + w] = (a0 + b0) + (a1 + b1);
        __syncthreads();  // bar A: all partials in sp

        // stage 2: warp w reduces its column; 4 partials/lane (8-bcast banks)
        // then 3 bfly shfls; lane 0 applies the ACTIVATION here (parallel
        // across all 32 warps -> off the serial tail)
        {
            const float* spc = spb + w * 33 + jj;
            float s = (spc[0] + spc[8]) + (spc[16] + spc[24]);
            s += __shfl_xor_sync(0xffffffffu, s, 4);
            s += __shfl_xor_sync(0xffffffffu, s, 2);
            s += __shfl_xor_sync(0xffffffffu, s, 1);
            if (l == 0) {
                const float z  = s + zxv;
                const int   q  = w >> 3;
                if (q == 2) {               // g gate: tanh
                    const float zc = fminf(fmaxf(z, -15.f), 15.f);
                    const float ee = __expf(2.f * zc);
                    zs[w] = __fdividef(ee - 1.f, ee + 1.f);
                } else {                    // i,f,o gates: sigmoid
                    const float ee = __expf(-z);
                    zs[w] = __fdividef(1.f, 1.f + ee);
                }
            }
        }
        __syncthreads();  // bar B: activated gate values ready

        // final: warp 0, lanes 0..7 update cell and publish
        if (w == 0 && l < 8) {
            const float ig = zs[l],      fg = zs[8 + l];
            const float gg = zs[16 + l], og = zs[24 + l];
            const float c2 = fg * cst + ig * gg;
            cst = c2;
            const float cc = fminf(fmaxf(c2, -15.f), 15.f);
            const float ec = __expf(2.f * cc);
            const float h  = og * __fdividef(ec - 1.f, ec + 1.f);
            // publish FIRST: one coalesced 64B wavefront (8 lanes x 8B)
            unsigned long long pkw;
            asm("mov.b64 %0, {%1, %2};"
                : "=l"(pkw) : "f"(h), "r"((unsigned)(t + 1)));
            asm volatile("st.volatile.global.u64 [%0], %1;"
                         :: "l"(&g_hpk[(t + 1) & 1][u0 + l]), "l"(pkw)
                         : "memory");
            out[(size_t)t * U_HID + u0 + l] = h;    // off critical path
        }
        zxv = zxn;
        // no trailing barrier: zs(t+1) writes happen after bar A(t+1), which
        // warp 0 only reaches after gates; sp reuse is parity-buffered.
    }
}

// ============================================================================
extern "C" void kernel_launch(void* const* d_in, const int* in_sizes, int n_in,
                              void* d_out, int out_size) {
    const float* x    = (const float*)d_in[0];  // [1, 32768, 1024]
    const float* kw   = (const float*)d_in[1];  // [1024, 4096]
    const float* rw   = (const float*)d_in[2];  // [1024, 4096]
    const float* bias = (const float*)d_in[3];  // [4096]
    float* out = (float*)d_out;                 // [1, 32768, 1024]

    int sms = 148;
    cudaDeviceGetAttribute(&sms, cudaDevAttrMultiProcessorCount, 0);
    int nGemm = sms - N_LSTM_CTAS;              // producer CTAs on spare SMs
    if (nGemm < 1) nGemm = 1;

    init_state<<<1, 1024>>>();
    mega<<<N_LSTM_CTAS + nGemm, 1024>>>(x, kw, bias, rw, out, nGemm);
}